// round 5
// baseline (speedup 1.0000x reference)
#include <cuda_runtime.h>
#include <cstdint>
#include <math.h>

#define B_TOTAL 16384
#define F_FIELDS 39
#define E_DIM 64
#define U_DIM 128
#define BTILE 128
#define THREADS 512
#define NPAIR 2080
#define KPAD  2112
#define NCHUNK 33
#define FSTR 65
#define ASTR 68
#define BSTR 68
#define ABUF 8704            // 128*68 floats per A/B buffer
#define SMEM_FLOATS (8320 + 4*ABUF + KPAD)
#define SMEM_BYTES  (SMEM_FLOATS * 4)

__device__ float    g_fsum[B_TOTAL * E_DIM];
__device__ unsigned g_T[U_DIM * KPAD];     // rna-tf32 bits of packed symmetric W (perm layout)
__device__ unsigned g_pair[KPAD];          // (i<<8)|j per PERMUTED packed k index

__device__ __forceinline__ unsigned f2tf(float x) {
    unsigned y; asm("cvt.rna.tf32.f32 %0, %1;" : "=r"(y) : "f"(x)); return y;
}
__device__ __forceinline__ uint32_t smem_u32(const void* p) {
    uint32_t a;
    asm("{ .reg .u64 t; cvta.to.shared.u64 t, %1; cvt.u32.u64 %0, t; }" : "=r"(a) : "l"(p));
    return a;
}
__device__ __forceinline__ void cp16(uint32_t dst, const void* src) {
    asm volatile("cp.async.cg.shared.global [%0], [%1], 16;" :: "r"(dst), "l"(src) : "memory");
}
__device__ __forceinline__ void cp_commit() {
    asm volatile("cp.async.commit_group;" ::: "memory");
}
__device__ __forceinline__ void cp_wait0() {
    asm volatile("cp.async.wait_group 0;" ::: "memory");
}
__device__ __forceinline__ void mma8(float* c, unsigned a0, unsigned a1,
                                     unsigned a2, unsigned a3,
                                     unsigned b0, unsigned b1) {
    asm volatile(
        "mma.sync.aligned.m16n8k8.row.col.f32.tf32.tf32.f32 "
        "{%0,%1,%2,%3}, {%4,%5,%6,%7}, {%8,%9}, {%0,%1,%2,%3};"
        : "+f"(c[0]), "+f"(c[1]), "+f"(c[2]), "+f"(c[3])
        : "r"(a0), "r"(a1), "r"(a2), "r"(a3), "r"(b0), "r"(b1));
}

// ---------------- pair table: packed upper-tri (i<=j), k-permuted in 8-groups ----------------
// position g*8+n holds original packed index g*8 + (n>>1) + 4*(n&1), so that the
// mma operand pair (k4, k4+4) sits at contiguous columns (2*k4, 2*k4+1) -> LDS.64.
__global__ void pairs_kernel() {
    int t = blockIdx.x * blockDim.x + threadIdx.x;
    if (t >= KPAD) return;
    int g = t >> 3, n = t & 7;
    int src = g * 8 + (n >> 1) + ((n & 1) << 2);
    unsigned val = 0;
    if (src < NPAIR) {
        double d = 129.0 * 129.0 - 8.0 * (double)src;
        int i = (int)((129.0 - sqrt(d)) * 0.5);
        if (i < 0) i = 0; if (i > 63) i = 63;
        while (i > 0  && i * (129 - i) / 2 > src) --i;
        while (i < 63 && (i + 1) * (128 - i) / 2 <= src) ++i;
        int j = i + (src - i * (129 - i) / 2);
        val = ((unsigned)i << 8) | (unsigned)j;
    }
    g_pair[t] = val;
}

// ---------------- feat_sum over F ----------------
__global__ void fsum_kernel(const float* __restrict__ embeds) {
    int idx = blockIdx.x * blockDim.x + threadIdx.x;
    int b = idx >> 4;
    int e4 = idx & 15;
    const float4* p = reinterpret_cast<const float4*>(embeds)
                      + (size_t)b * (F_FIELDS * E_DIM / 4) + e4;
    float4 s = make_float4(0.f, 0.f, 0.f, 0.f);
#pragma unroll
    for (int f = 0; f < F_FIELDS; ++f) {
        float4 v = p[f * (E_DIM / 4)];
        s.x += v.x; s.y += v.y; s.z += v.z; s.w += v.w;
    }
    reinterpret_cast<float4*>(g_fsum)[idx] = s;
}

// ---------------- packed symmetric T[u,k] = rna_tf32(W_ij + W_ji), perm layout ----------------
__global__ void tconv_kernel(const float* __restrict__ W) {
    int idx = blockIdx.x * blockDim.x + threadIdx.x;   // u*KPAD + k
    int u = idx / KPAD;
    int k = idx - u * KPAD;
    unsigned p = g_pair[k];
    float v = 0.f;
    if (p != 0 || k == 0) {
        int i = p >> 8, j = p & 255;
        v = W[u * 4096 + i * 64 + j];
        if (i != j) v += W[u * 4096 + j * 64 + i];
    }
    g_T[idx] = f2tf(v);
}

// ---------------- main GEMM: C[128b x 128u] += A[128 x 64] * B[64 x 128] ----------------
// 512 threads, 16 warps in 4m x 4n grid; warp tile 32 rows x 32 cols.
__global__ void __launch_bounds__(THREADS, 1)
quad_kernel(float* __restrict__ out) {
    extern __shared__ float sm[];
    float*    sF = sm;                         // 128*65
    float*    sA = sm + 8320;                  // 2 * ABUF
    float*    sB = sm + 8320 + 2 * ABUF;       // 2 * ABUF
    unsigned* sP = (unsigned*)(sm + 8320 + 4 * ABUF);  // KPAD

    const int tid  = threadIdx.x;
    const int lane = tid & 31;
    const int warp = tid >> 5;
    const int l4 = lane >> 2, k4 = lane & 3;
    const int row_base = (warp & 3) * 32;
    const int col_base = (warp >> 2) * 32;
    const int b0 = blockIdx.x * BTILE;
    const int r  = tid & 127;
    const int kh = (tid >> 7) * 16;            // 16-col slice per thread

    const uint32_t sB_u = smem_u32(sB);

    // ---- stage f tile (padded stride 65 -> conflict-free column reads) ----
    {
        const float4* src = reinterpret_cast<const float4*>(
            g_fsum + (size_t)(b0 + r) * E_DIM + kh);
        float tmp[16];
#pragma unroll
        for (int t = 0; t < 4; ++t) {
            float4 v = src[t];
            tmp[4*t] = v.x; tmp[4*t+1] = v.y; tmp[4*t+2] = v.z; tmp[4*t+3] = v.w;
        }
#pragma unroll
        for (int t = 0; t < 16; ++t) sF[r * FSTR + kh + t] = tmp[t];
    }
    for (int k = tid; k < KPAD; k += THREADS) sP[k] = g_pair[k];

    // ---- prologue: B chunk 0 ----
    {
        const unsigned* src = g_T + (size_t)r * KPAD + kh;
        uint32_t dst = sB_u + (uint32_t)(r * BSTR + kh) * 4u;
#pragma unroll
        for (int q = 0; q < 4; ++q) cp16(dst + 16u * q, src + 4 * q);
        cp_commit();
    }
    cp_wait0();
    __syncthreads();

    // ---- gen A chunk 0 ----
    {
        const int fb = r * FSTR;
        float* dst = sA + r * ASTR + kh;
#pragma unroll
        for (int q = 0; q < 4; ++q) {
            unsigned p0 = sP[kh + 4*q + 0], p1 = sP[kh + 4*q + 1];
            unsigned p2 = sP[kh + 4*q + 2], p3 = sP[kh + 4*q + 3];
            float4 v;
            v.x = __uint_as_float(f2tf(sF[fb + (p0 >> 8)] * sF[fb + (p0 & 255)]));
            v.y = __uint_as_float(f2tf(sF[fb + (p1 >> 8)] * sF[fb + (p1 & 255)]));
            v.z = __uint_as_float(f2tf(sF[fb + (p2 >> 8)] * sF[fb + (p2 & 255)]));
            v.w = __uint_as_float(f2tf(sF[fb + (p3 >> 8)] * sF[fb + (p3 & 255)]));
            *reinterpret_cast<float4*>(dst + 4*q) = v;
        }
    }
    __syncthreads();

    float acc[2][4][4];
#pragma unroll
    for (int mt = 0; mt < 2; ++mt)
#pragma unroll
        for (int nt = 0; nt < 4; ++nt)
#pragma unroll
            for (int x = 0; x < 4; ++x) acc[mt][nt][x] = 0.f;

#pragma unroll 1
    for (int c = 0; c < NCHUNK; ++c) {
        const int cur = c & 1, nxt = cur ^ 1;

        // stage B(c+1) into the other buffer
        if (c + 1 < NCHUNK) {
            const unsigned* src = g_T + (size_t)r * KPAD + (c + 1) * 64 + kh;
            uint32_t dst = sB_u + (uint32_t)(nxt * ABUF + r * BSTR + kh) * 4u;
#pragma unroll
            for (int q = 0; q < 4; ++q) cp16(dst + 16u * q, src + 4 * q);
            cp_commit();
        }

        // ---- mma over chunk c (all fragment loads are LDS.64 pairs) ----
        const float* A = sA + cur * ABUF;
        const float* B = sB + cur * ABUF;
#pragma unroll
        for (int kk = 0; kk < 8; ++kk) {
            const int kcol = kk * 8 + k4 * 2;
            float2 a0[2], a1[2];
#pragma unroll
            for (int mt = 0; mt < 2; ++mt) {
                const float* ap = A + (row_base + mt * 16 + l4) * ASTR + kcol;
                a0[mt] = *reinterpret_cast<const float2*>(ap);
                a1[mt] = *reinterpret_cast<const float2*>(ap + 8 * ASTR);
            }
#pragma unroll
            for (int nt = 0; nt < 4; ++nt) {
                float2 bb = *reinterpret_cast<const float2*>(
                    B + (col_base + nt * 8 + l4) * BSTR + kcol);
                unsigned bf0 = __float_as_uint(bb.x);
                unsigned bf1 = __float_as_uint(bb.y);
#pragma unroll
                for (int mt = 0; mt < 2; ++mt)
                    mma8(acc[mt][nt],
                         __float_as_uint(a0[mt].x), __float_as_uint(a1[mt].x),
                         __float_as_uint(a0[mt].y), __float_as_uint(a1[mt].y),
                         bf0, bf1);
            }
        }

        // ---- gen A(c+1) into the other buffer ----
        if (c + 1 < NCHUNK) {
            const int kb = (c + 1) * 64 + kh;
            const int fb = r * FSTR;
            float* dst = sA + nxt * ABUF + r * ASTR + kh;
#pragma unroll
            for (int q = 0; q < 4; ++q) {
                unsigned p0 = sP[kb + 4*q + 0], p1 = sP[kb + 4*q + 1];
                unsigned p2 = sP[kb + 4*q + 2], p3 = sP[kb + 4*q + 3];
                float4 v;
                v.x = __uint_as_float(f2tf(sF[fb + (p0 >> 8)] * sF[fb + (p0 & 255)]));
                v.y = __uint_as_float(f2tf(sF[fb + (p1 >> 8)] * sF[fb + (p1 & 255)]));
                v.z = __uint_as_float(f2tf(sF[fb + (p2 >> 8)] * sF[fb + (p2 & 255)]));
                v.w = __uint_as_float(f2tf(sF[fb + (p3 >> 8)] * sF[fb + (p3 & 255)]));
                *reinterpret_cast<float4*>(dst + 4*q) = v;
            }
        }
        cp_wait0();
        __syncthreads();
    }

    // ---- epilogue: direct STG of C fragments ----
#pragma unroll
    for (int mt = 0; mt < 2; ++mt) {
#pragma unroll
        for (int nt = 0; nt < 4; ++nt) {
            const int rr = b0 + row_base + mt * 16 + l4;
            const int cc = col_base + nt * 8 + k4 * 2;
            float2 v0 = make_float2(acc[mt][nt][0], acc[mt][nt][1]);
            float2 v1 = make_float2(acc[mt][nt][2], acc[mt][nt][3]);
            *reinterpret_cast<float2*>(out + (size_t)rr * U_DIM + cc) = v0;
            *reinterpret_cast<float2*>(out + (size_t)(rr + 8) * U_DIM + cc) = v1;
        }
    }
}

extern "C" void kernel_launch(void* const* d_in, const int* in_sizes, int n_in,
                              void* d_out, int out_size) {
    const float* embeds = (const float*)d_in[0];   // (16384, 39, 64)
    const float* W      = (const float*)d_in[1];   // (128, 64, 64)
    float* out          = (float*)d_out;           // (16384, 128)

    static int smem_set = 0;
    if (!smem_set) {
        cudaFuncSetAttribute(quad_kernel,
                             cudaFuncAttributeMaxDynamicSharedMemorySize, SMEM_BYTES);
        smem_set = 1;
    }

    pairs_kernel<<<(KPAD + 255) / 256, 256>>>();
    fsum_kernel<<<(B_TOTAL * (E_DIM / 4)) / 256, 256>>>(embeds);
    tconv_kernel<<<(U_DIM * KPAD) / 256, 256>>>(W);
    quad_kernel<<<B_TOTAL / BTILE, THREADS, SMEM_BYTES>>>(out);
}

// round 6
// speedup vs baseline: 1.0777x; 1.0777x over previous
#include <cuda_runtime.h>
#include <cstdint>
#include <math.h>

#define B_TOTAL 16384
#define F_FIELDS 39
#define E_DIM 64
#define U_DIM 128
#define BTILE 128
#define THREADS 256
#define NPAIR 2080
#define KPAD  2112
#define NCHUNK 33
#define FSTR 65
#define ASTR 72
#define BSTR 72
#define ABUF 9216            // 128*72 floats per A/B buffer
#define SMEM_FLOATS (8320 + 4*ABUF + KPAD)
#define SMEM_BYTES  (SMEM_FLOATS * 4)

__device__ float    g_fsum[B_TOTAL * E_DIM];
__device__ unsigned g_T[U_DIM * KPAD];     // rna-tf32 bits of packed symmetric W (perm layout)
__device__ unsigned g_pair[KPAD];          // (i<<8)|j per PERMUTED packed k index

__device__ __forceinline__ unsigned f2tf(float x) {
    unsigned y; asm("cvt.rna.tf32.f32 %0, %1;" : "=r"(y) : "f"(x)); return y;
}
__device__ __forceinline__ uint32_t smem_u32(const void* p) {
    uint32_t a;
    asm("{ .reg .u64 t; cvta.to.shared.u64 t, %1; cvt.u32.u64 %0, t; }" : "=r"(a) : "l"(p));
    return a;
}
__device__ __forceinline__ void cp16(uint32_t dst, const void* src) {
    asm volatile("cp.async.cg.shared.global [%0], [%1], 16;" :: "r"(dst), "l"(src) : "memory");
}
__device__ __forceinline__ void cp_commit() {
    asm volatile("cp.async.commit_group;" ::: "memory");
}
__device__ __forceinline__ void cp_wait0() {
    asm volatile("cp.async.wait_group 0;" ::: "memory");
}
__device__ __forceinline__ void mma8(float* c, unsigned a0, unsigned a1,
                                     unsigned a2, unsigned a3,
                                     unsigned b0, unsigned b1) {
    asm volatile(
        "mma.sync.aligned.m16n8k8.row.col.f32.tf32.tf32.f32 "
        "{%0,%1,%2,%3}, {%4,%5,%6,%7}, {%8,%9}, {%0,%1,%2,%3};"
        : "+f"(c[0]), "+f"(c[1]), "+f"(c[2]), "+f"(c[3])
        : "r"(a0), "r"(a1), "r"(a2), "r"(a3), "r"(b0), "r"(b1));
}

// ---------------- pair table: packed upper-tri (i<=j), k-permuted in 8-groups ----------------
// position g*8+n holds original packed index g*8 + (n>>1) + 4*(n&1), so that the
// mma operand pair (k4, k4+4) sits at contiguous columns (2*k4, 2*k4+1) -> LDS.64.
__global__ void pairs_kernel() {
    int t = blockIdx.x * blockDim.x + threadIdx.x;
    if (t >= KPAD) return;
    int g = t >> 3, n = t & 7;
    int src = g * 8 + (n >> 1) + ((n & 1) << 2);
    unsigned val = 0;
    if (src < NPAIR) {
        double d = 129.0 * 129.0 - 8.0 * (double)src;
        int i = (int)((129.0 - sqrt(d)) * 0.5);
        if (i < 0) i = 0; if (i > 63) i = 63;
        while (i > 0  && i * (129 - i) / 2 > src) --i;
        while (i < 63 && (i + 1) * (128 - i) / 2 <= src) ++i;
        int j = i + (src - i * (129 - i) / 2);
        val = ((unsigned)i << 8) | (unsigned)j;
    }
    g_pair[t] = val;
}

// ---------------- feat_sum over F ----------------
__global__ void fsum_kernel(const float* __restrict__ embeds) {
    int idx = blockIdx.x * blockDim.x + threadIdx.x;
    int b = idx >> 4;
    int e4 = idx & 15;
    const float4* p = reinterpret_cast<const float4*>(embeds)
                      + (size_t)b * (F_FIELDS * E_DIM / 4) + e4;
    float4 s = make_float4(0.f, 0.f, 0.f, 0.f);
#pragma unroll
    for (int f = 0; f < F_FIELDS; ++f) {
        float4 v = p[f * (E_DIM / 4)];
        s.x += v.x; s.y += v.y; s.z += v.z; s.w += v.w;
    }
    reinterpret_cast<float4*>(g_fsum)[idx] = s;
}

// ---------------- packed symmetric T[u,k] = rna_tf32(W_ij + W_ji), perm layout ----------------
__global__ void tconv_kernel(const float* __restrict__ W) {
    int idx = blockIdx.x * blockDim.x + threadIdx.x;   // u*KPAD + k
    int u = idx / KPAD;
    int k = idx - u * KPAD;
    unsigned p = g_pair[k];
    float v = 0.f;
    if (p != 0 || k == 0) {
        int i = p >> 8, j = p & 255;
        v = W[u * 4096 + i * 64 + j];
        if (i != j) v += W[u * 4096 + j * 64 + i];
    }
    g_T[idx] = f2tf(v);
}

// ---------------- main GEMM: C[128b x 128u] += A[128 x 64] * B[64 x 128] ----------------
// 256 threads, 8 warps in 4m x 2n grid; warp tile 32 rows x 64 cols.
// All fragment loads are conflict-free LDS.64 (stride 72), register
// double-buffered across kk to hide LDS latency under the MMA stream.
__global__ void __launch_bounds__(THREADS, 1)
quad_kernel(float* __restrict__ out) {
    extern __shared__ float sm[];
    float*    sF = sm;                         // 128*65
    float*    sA = sm + 8320;                  // 2 * ABUF
    float*    sB = sm + 8320 + 2 * ABUF;       // 2 * ABUF
    unsigned* sP = (unsigned*)(sm + 8320 + 4 * ABUF);  // KPAD

    const int tid  = threadIdx.x;
    const int lane = tid & 31;
    const int warp = tid >> 5;
    const int l4 = lane >> 2, k4 = lane & 3;
    const int row_base = (warp & 3) * 32;     // 4-way m split
    const int col_base = (warp >> 2) * 64;    // 2-way n split
    const int b0 = blockIdx.x * BTILE;
    const int r  = tid & 127;
    const int kh = (tid >> 7) * 32;            // 32-col slice per thread

    const uint32_t sB_u = smem_u32(sB);

    // ---- stage f tile (padded stride 65 -> conflict-free gen reads) ----
    {
        const float4* src = reinterpret_cast<const float4*>(
            g_fsum + (size_t)(b0 + r) * E_DIM + kh);
        float tmp[32];
#pragma unroll
        for (int t = 0; t < 8; ++t) {
            float4 v = src[t];
            tmp[4*t] = v.x; tmp[4*t+1] = v.y; tmp[4*t+2] = v.z; tmp[4*t+3] = v.w;
        }
#pragma unroll
        for (int t = 0; t < 32; ++t) sF[r * FSTR + kh + t] = tmp[t];
    }
    for (int k = tid; k < KPAD; k += THREADS) sP[k] = g_pair[k];

    // ---- prologue: B chunk 0 ----
    {
        const unsigned* src = g_T + (size_t)r * KPAD + kh;
        uint32_t dst = sB_u + (uint32_t)(r * BSTR + kh) * 4u;
#pragma unroll
        for (int q = 0; q < 8; ++q) cp16(dst + 16u * q, src + 4 * q);
        cp_commit();
    }
    cp_wait0();
    __syncthreads();

    // ---- gen A chunk 0 ----
    {
        const int fb = r * FSTR;
        float* dst = sA + r * ASTR + kh;
#pragma unroll
        for (int q = 0; q < 8; ++q) {
            unsigned p0 = sP[kh + 4*q + 0], p1 = sP[kh + 4*q + 1];
            unsigned p2 = sP[kh + 4*q + 2], p3 = sP[kh + 4*q + 3];
            float4 v;
            v.x = __uint_as_float(f2tf(sF[fb + (p0 >> 8)] * sF[fb + (p0 & 255)]));
            v.y = __uint_as_float(f2tf(sF[fb + (p1 >> 8)] * sF[fb + (p1 & 255)]));
            v.z = __uint_as_float(f2tf(sF[fb + (p2 >> 8)] * sF[fb + (p2 & 255)]));
            v.w = __uint_as_float(f2tf(sF[fb + (p3 >> 8)] * sF[fb + (p3 & 255)]));
            *reinterpret_cast<float4*>(dst + 4*q) = v;
        }
    }
    __syncthreads();

    float acc[2][8][4];
#pragma unroll
    for (int mt = 0; mt < 2; ++mt)
#pragma unroll
        for (int nt = 0; nt < 8; ++nt)
#pragma unroll
            for (int x = 0; x < 4; ++x) acc[mt][nt][x] = 0.f;

#pragma unroll 1
    for (int c = 0; c < NCHUNK; ++c) {
        const int cur = c & 1, nxt = cur ^ 1;

        // stage B(c+1) into the other buffer
        if (c + 1 < NCHUNK) {
            const unsigned* src = g_T + (size_t)r * KPAD + (c + 1) * 64 + kh;
            uint32_t dst = sB_u + (uint32_t)(nxt * ABUF + r * BSTR + kh) * 4u;
#pragma unroll
            for (int q = 0; q < 8; ++q) cp16(dst + 16u * q, src + 4 * q);
            cp_commit();
        }

        // ---- mma over chunk c, register double-buffered fragments ----
        const float* A = sA + cur * ABUF;
        const float* B = sB + cur * ABUF;

        float2 Af[2][2][2];   // [buf][mt][row l4 / l4+8]
        float2 Bf[2][8];      // [buf][nt]
        {
            const int kcol = k4 * 2;   // kk = 0
#pragma unroll
            for (int mt = 0; mt < 2; ++mt) {
                const float* ap = A + (row_base + mt * 16 + l4) * ASTR + kcol;
                Af[0][mt][0] = *reinterpret_cast<const float2*>(ap);
                Af[0][mt][1] = *reinterpret_cast<const float2*>(ap + 8 * ASTR);
            }
#pragma unroll
            for (int nt = 0; nt < 8; ++nt)
                Bf[0][nt] = *reinterpret_cast<const float2*>(
                    B + (col_base + nt * 8 + l4) * BSTR + kcol);
        }
#pragma unroll
        for (int kk = 0; kk < 8; ++kk) {
            const int cb = kk & 1, nb = cb ^ 1;
            if (kk < 7) {
                const int kcol = (kk + 1) * 8 + k4 * 2;
#pragma unroll
                for (int mt = 0; mt < 2; ++mt) {
                    const float* ap = A + (row_base + mt * 16 + l4) * ASTR + kcol;
                    Af[nb][mt][0] = *reinterpret_cast<const float2*>(ap);
                    Af[nb][mt][1] = *reinterpret_cast<const float2*>(ap + 8 * ASTR);
                }
#pragma unroll
                for (int nt = 0; nt < 8; ++nt)
                    Bf[nb][nt] = *reinterpret_cast<const float2*>(
                        B + (col_base + nt * 8 + l4) * BSTR + kcol);
            }
#pragma unroll
            for (int nt = 0; nt < 8; ++nt) {
                unsigned bf0 = __float_as_uint(Bf[cb][nt].x);
                unsigned bf1 = __float_as_uint(Bf[cb][nt].y);
#pragma unroll
                for (int mt = 0; mt < 2; ++mt)
                    mma8(acc[mt][nt],
                         __float_as_uint(Af[cb][mt][0].x),
                         __float_as_uint(Af[cb][mt][1].x),
                         __float_as_uint(Af[cb][mt][0].y),
                         __float_as_uint(Af[cb][mt][1].y),
                         bf0, bf1);
            }
        }

        // ---- gen A(c+1) into the other buffer ----
        if (c + 1 < NCHUNK) {
            const int kb = (c + 1) * 64 + kh;
            const int fb = r * FSTR;
            float* dst = sA + nxt * ABUF + r * ASTR + kh;
#pragma unroll
            for (int q = 0; q < 8; ++q) {
                unsigned p0 = sP[kb + 4*q + 0], p1 = sP[kb + 4*q + 1];
                unsigned p2 = sP[kb + 4*q + 2], p3 = sP[kb + 4*q + 3];
                float4 v;
                v.x = __uint_as_float(f2tf(sF[fb + (p0 >> 8)] * sF[fb + (p0 & 255)]));
                v.y = __uint_as_float(f2tf(sF[fb + (p1 >> 8)] * sF[fb + (p1 & 255)]));
                v.z = __uint_as_float(f2tf(sF[fb + (p2 >> 8)] * sF[fb + (p2 & 255)]));
                v.w = __uint_as_float(f2tf(sF[fb + (p3 >> 8)] * sF[fb + (p3 & 255)]));
                *reinterpret_cast<float4*>(dst + 4*q) = v;
            }
        }
        cp_wait0();
        __syncthreads();
    }

    // ---- epilogue: direct STG of C fragments ----
#pragma unroll
    for (int mt = 0; mt < 2; ++mt) {
#pragma unroll
        for (int nt = 0; nt < 8; ++nt) {
            const int rr = b0 + row_base + mt * 16 + l4;
            const int cc = col_base + nt * 8 + k4 * 2;
            float2 v0 = make_float2(acc[mt][nt][0], acc[mt][nt][1]);
            float2 v1 = make_float2(acc[mt][nt][2], acc[mt][nt][3]);
            *reinterpret_cast<float2*>(out + (size_t)rr * U_DIM + cc) = v0;
            *reinterpret_cast<float2*>(out + (size_t)(rr + 8) * U_DIM + cc) = v1;
        }
    }
}

extern "C" void kernel_launch(void* const* d_in, const int* in_sizes, int n_in,
                              void* d_out, int out_size) {
    const float* embeds = (const float*)d_in[0];   // (16384, 39, 64)
    const float* W      = (const float*)d_in[1];   // (128, 64, 64)
    float* out          = (float*)d_out;           // (16384, 128)

    static int smem_set = 0;
    if (!smem_set) {
        cudaFuncSetAttribute(quad_kernel,
                             cudaFuncAttributeMaxDynamicSharedMemorySize, SMEM_BYTES);
        smem_set = 1;
    }

    pairs_kernel<<<(KPAD + 255) / 256, 256>>>();
    fsum_kernel<<<(B_TOTAL * (E_DIM / 4)) / 256, 256>>>(embeds);
    tconv_kernel<<<(U_DIM * KPAD) / 256, 256>>>(W);
    quad_kernel<<<B_TOTAL / BTILE, THREADS, SMEM_BYTES>>>(out);
}

// round 7
// speedup vs baseline: 1.1211x; 1.0403x over previous
#include <cuda_runtime.h>
#include <cstdint>
#include <math.h>

#define B_TOTAL 16384
#define F_FIELDS 39
#define E_DIM 64
#define U_DIM 128
#define BTILE 128
#define THREADS 512
#define NPAIR 2080
#define KPAD  2112
#define NCHUNK 33
#define FSTR 65
#define ASTR 72
#define BSTR 72
#define ABUF 9216            // 128*72 floats per A/B buffer
#define SMEM_FLOATS (8320 + 4*ABUF + KPAD)
#define SMEM_BYTES  (SMEM_FLOATS * 4)

__device__ float    g_fsum[B_TOTAL * E_DIM];
__device__ unsigned g_T[U_DIM * KPAD];     // rna-tf32 bits of packed symmetric W (perm layout)
__device__ unsigned g_pair[KPAD];          // (i<<8)|j per PERMUTED packed k index

__device__ __forceinline__ unsigned f2tf(float x) {
    unsigned y; asm("cvt.rna.tf32.f32 %0, %1;" : "=r"(y) : "f"(x)); return y;
}
__device__ __forceinline__ uint32_t smem_u32(const void* p) {
    uint32_t a;
    asm("{ .reg .u64 t; cvta.to.shared.u64 t, %1; cvt.u32.u64 %0, t; }" : "=r"(a) : "l"(p));
    return a;
}
__device__ __forceinline__ void cp16(uint32_t dst, const void* src) {
    asm volatile("cp.async.cg.shared.global [%0], [%1], 16;" :: "r"(dst), "l"(src) : "memory");
}
__device__ __forceinline__ void cp_commit() {
    asm volatile("cp.async.commit_group;" ::: "memory");
}
__device__ __forceinline__ void cp_wait0() {
    asm volatile("cp.async.wait_group 0;" ::: "memory");
}
__device__ __forceinline__ void mma8(float* c, unsigned a0, unsigned a1,
                                     unsigned a2, unsigned a3,
                                     unsigned b0, unsigned b1) {
    asm volatile(
        "mma.sync.aligned.m16n8k8.row.col.f32.tf32.tf32.f32 "
        "{%0,%1,%2,%3}, {%4,%5,%6,%7}, {%8,%9}, {%0,%1,%2,%3};"
        : "+f"(c[0]), "+f"(c[1]), "+f"(c[2]), "+f"(c[3])
        : "r"(a0), "r"(a1), "r"(a2), "r"(a3), "r"(b0), "r"(b1));
}

// ---------------- pair table: packed upper-tri (i<=j), k-permuted in 8-groups ----------------
__global__ void pairs_kernel() {
    int t = blockIdx.x * blockDim.x + threadIdx.x;
    if (t >= KPAD) return;
    int g = t >> 3, n = t & 7;
    int src = g * 8 + (n >> 1) + ((n & 1) << 2);
    unsigned val = 0;
    if (src < NPAIR) {
        double d = 129.0 * 129.0 - 8.0 * (double)src;
        int i = (int)((129.0 - sqrt(d)) * 0.5);
        if (i < 0) i = 0; if (i > 63) i = 63;
        while (i > 0  && i * (129 - i) / 2 > src) --i;
        while (i < 63 && (i + 1) * (128 - i) / 2 <= src) ++i;
        int j = i + (src - i * (129 - i) / 2);
        val = ((unsigned)i << 8) | (unsigned)j;
    }
    g_pair[t] = val;
}

// ---------------- feat_sum over F ----------------
__global__ void fsum_kernel(const float* __restrict__ embeds) {
    int idx = blockIdx.x * blockDim.x + threadIdx.x;
    int b = idx >> 4;
    int e4 = idx & 15;
    const float4* p = reinterpret_cast<const float4*>(embeds)
                      + (size_t)b * (F_FIELDS * E_DIM / 4) + e4;
    float4 s = make_float4(0.f, 0.f, 0.f, 0.f);
#pragma unroll
    for (int f = 0; f < F_FIELDS; ++f) {
        float4 v = p[f * (E_DIM / 4)];
        s.x += v.x; s.y += v.y; s.z += v.z; s.w += v.w;
    }
    reinterpret_cast<float4*>(g_fsum)[idx] = s;
}

// ---------------- packed symmetric T[u,k] = rna_tf32(W_ij + W_ji), perm layout ----------------
__global__ void tconv_kernel(const float* __restrict__ W) {
    int idx = blockIdx.x * blockDim.x + threadIdx.x;   // u*KPAD + k
    int u = idx / KPAD;
    int k = idx - u * KPAD;
    unsigned p = g_pair[k];
    float v = 0.f;
    if (p != 0 || k == 0) {
        int i = p >> 8, j = p & 255;
        v = W[u * 4096 + i * 64 + j];
        if (i != j) v += W[u * 4096 + j * 64 + i];
    }
    g_T[idx] = f2tf(v);
}

// ---------------- main GEMM: C[128b x 128u] += A[128 x 64] * B[64 x 128] ----------------
// 512 threads = 16 warps: 8 tile-warps (4m x 2n, 32x64 tiles) x 2 k-split.
// Warp (t, kw) computes kk in [kw*4, kw*4+4); partials summed via smem epilogue.
__global__ void __launch_bounds__(THREADS, 1)
quad_kernel(float* __restrict__ out) {
    extern __shared__ float sm[];
    float*    sF = sm;                         // 128*65
    float*    sA = sm + 8320;                  // 2 * ABUF (also epilogue staging)
    float*    sB = sm + 8320 + 2 * ABUF;       // 2 * ABUF
    unsigned* sP = (unsigned*)(sm + 8320 + 4 * ABUF);  // KPAD

    const int tid  = threadIdx.x;
    const int lane = tid & 31;
    const int warp = tid >> 5;
    const int twarp = warp & 7;               // tile-warp id
    const int kw    = warp >> 3;               // k-split id (0/1)
    const int l4 = lane >> 2, k4 = lane & 3;
    const int row_base = (twarp & 3) * 32;     // 4-way m split
    const int col_base = (twarp >> 2) * 64;    // 2-way n split
    const int b0 = blockIdx.x * BTILE;
    const int r  = tid & 127;
    const int kh = (tid >> 7) * 16;            // 16-col slice per thread

    const uint32_t sB_u = smem_u32(sB);

    // ---- stage f tile (padded stride 65 -> conflict-free gen reads) ----
    {
        const float4* src = reinterpret_cast<const float4*>(
            g_fsum + (size_t)(b0 + r) * E_DIM + kh);
#pragma unroll
        for (int t = 0; t < 4; ++t) {
            float4 v = src[t];
            sF[r * FSTR + kh + 4*t + 0] = v.x;
            sF[r * FSTR + kh + 4*t + 1] = v.y;
            sF[r * FSTR + kh + 4*t + 2] = v.z;
            sF[r * FSTR + kh + 4*t + 3] = v.w;
        }
    }
    for (int k = tid; k < KPAD; k += THREADS) sP[k] = g_pair[k];

    // ---- prologue: B chunk 0 ----
    {
        const unsigned* src = g_T + (size_t)r * KPAD + kh;
        uint32_t dst = sB_u + (uint32_t)(r * BSTR + kh) * 4u;
#pragma unroll
        for (int q = 0; q < 4; ++q) cp16(dst + 16u * q, src + 4 * q);
        cp_commit();
    }
    cp_wait0();
    __syncthreads();

    // ---- gen A chunk 0 ----
    {
        const int fb = r * FSTR;
        float* dst = sA + r * ASTR + kh;
#pragma unroll
        for (int q = 0; q < 4; ++q) {
            unsigned p0 = sP[kh + 4*q + 0], p1 = sP[kh + 4*q + 1];
            unsigned p2 = sP[kh + 4*q + 2], p3 = sP[kh + 4*q + 3];
            float4 v;
            v.x = __uint_as_float(f2tf(sF[fb + (p0 >> 8)] * sF[fb + (p0 & 255)]));
            v.y = __uint_as_float(f2tf(sF[fb + (p1 >> 8)] * sF[fb + (p1 & 255)]));
            v.z = __uint_as_float(f2tf(sF[fb + (p2 >> 8)] * sF[fb + (p2 & 255)]));
            v.w = __uint_as_float(f2tf(sF[fb + (p3 >> 8)] * sF[fb + (p3 & 255)]));
            *reinterpret_cast<float4*>(dst + 4*q) = v;
        }
    }
    __syncthreads();

    float acc[2][8][4];
#pragma unroll
    for (int mt = 0; mt < 2; ++mt)
#pragma unroll
        for (int nt = 0; nt < 8; ++nt)
#pragma unroll
            for (int x = 0; x < 4; ++x) acc[mt][nt][x] = 0.f;

#pragma unroll 1
    for (int c = 0; c < NCHUNK; ++c) {
        const int cur = c & 1, nxt = cur ^ 1;

        // issue next-chunk staging FIRST so its latency hides under MMAs
        if (c + 1 < NCHUNK) {
            const unsigned* src = g_T + (size_t)r * KPAD + (c + 1) * 64 + kh;
            uint32_t dst = sB_u + (uint32_t)(nxt * ABUF + r * BSTR + kh) * 4u;
#pragma unroll
            for (int q = 0; q < 4; ++q) cp16(dst + 16u * q, src + 4 * q);
            cp_commit();

            const int kb = (c + 1) * 64 + kh;
            const int fb = r * FSTR;
            float* adst = sA + nxt * ABUF + r * ASTR + kh;
#pragma unroll
            for (int q = 0; q < 4; ++q) {
                unsigned p0 = sP[kb + 4*q + 0], p1 = sP[kb + 4*q + 1];
                unsigned p2 = sP[kb + 4*q + 2], p3 = sP[kb + 4*q + 3];
                float4 v;
                v.x = __uint_as_float(f2tf(sF[fb + (p0 >> 8)] * sF[fb + (p0 & 255)]));
                v.y = __uint_as_float(f2tf(sF[fb + (p1 >> 8)] * sF[fb + (p1 & 255)]));
                v.z = __uint_as_float(f2tf(sF[fb + (p2 >> 8)] * sF[fb + (p2 & 255)]));
                v.w = __uint_as_float(f2tf(sF[fb + (p3 >> 8)] * sF[fb + (p3 & 255)]));
                *reinterpret_cast<float4*>(adst + 4*q) = v;
            }
        }

        // ---- mma over this warp's k-half of chunk c ----
        const float* A = sA + cur * ABUF;
        const float* B = sB + cur * ABUF;
#pragma unroll
        for (int kx = 0; kx < 4; ++kx) {
            const int kcol = (kw * 4 + kx) * 8 + k4 * 2;
            float2 a0[2], a1[2];
#pragma unroll
            for (int mt = 0; mt < 2; ++mt) {
                const float* ap = A + (row_base + mt * 16 + l4) * ASTR + kcol;
                a0[mt] = *reinterpret_cast<const float2*>(ap);
                a1[mt] = *reinterpret_cast<const float2*>(ap + 8 * ASTR);
            }
#pragma unroll
            for (int nt = 0; nt < 8; ++nt) {
                float2 bb = *reinterpret_cast<const float2*>(
                    B + (col_base + nt * 8 + l4) * BSTR + kcol);
                unsigned bf0 = __float_as_uint(bb.x);
                unsigned bf1 = __float_as_uint(bb.y);
#pragma unroll
                for (int mt = 0; mt < 2; ++mt)
                    mma8(acc[mt][nt],
                         __float_as_uint(a0[mt].x), __float_as_uint(a1[mt].x),
                         __float_as_uint(a0[mt].y), __float_as_uint(a1[mt].y),
                         bf0, bf1);
            }
        }
        cp_wait0();
        __syncthreads();
    }

    // ---- epilogue: sum k-split partials via smem, then STG ----
    // kw=1 warps stage their acc; kw=0 warps add and store.
    if (kw == 1) {
        const int idx = tid - 256;             // 0..255
        float4* sRed = reinterpret_cast<float4*>(sA);
#pragma unroll
        for (int mt = 0; mt < 2; ++mt)
#pragma unroll
            for (int nt = 0; nt < 8; ++nt) {
                int q = mt * 8 + nt;
                sRed[q * 256 + idx] = make_float4(acc[mt][nt][0], acc[mt][nt][1],
                                                  acc[mt][nt][2], acc[mt][nt][3]);
            }
    }
    __syncthreads();
    if (kw == 0) {
        const float4* sRed = reinterpret_cast<const float4*>(sA);
#pragma unroll
        for (int mt = 0; mt < 2; ++mt) {
#pragma unroll
            for (int nt = 0; nt < 8; ++nt) {
                int q = mt * 8 + nt;
                float4 p = sRed[q * 256 + tid];
                float2 v0 = make_float2(acc[mt][nt][0] + p.x, acc[mt][nt][1] + p.y);
                float2 v1 = make_float2(acc[mt][nt][2] + p.z, acc[mt][nt][3] + p.w);
                const int rr = b0 + row_base + mt * 16 + l4;
                const int cc = col_base + nt * 8 + k4 * 2;
                *reinterpret_cast<float2*>(out + (size_t)rr * U_DIM + cc) = v0;
                *reinterpret_cast<float2*>(out + (size_t)(rr + 8) * U_DIM + cc) = v1;
            }
        }
    }
}

extern "C" void kernel_launch(void* const* d_in, const int* in_sizes, int n_in,
                              void* d_out, int out_size) {
    const float* embeds = (const float*)d_in[0];   // (16384, 39, 64)
    const float* W      = (const float*)d_in[1];   // (128, 64, 64)
    float* out          = (float*)d_out;           // (16384, 128)

    static int smem_set = 0;
    if (!smem_set) {
        cudaFuncSetAttribute(quad_kernel,
                             cudaFuncAttributeMaxDynamicSharedMemorySize, SMEM_BYTES);
        smem_set = 1;
    }

    pairs_kernel<<<(KPAD + 255) / 256, 256>>>();
    fsum_kernel<<<(B_TOTAL * (E_DIM / 4)) / 256, 256>>>(embeds);
    tconv_kernel<<<(U_DIM * KPAD) / 256, 256>>>(W);
    quad_kernel<<<B_TOTAL / BTILE, THREADS, SMEM_BYTES>>>(out);
}